// round 16
// baseline (speedup 1.0000x reference)
#include <cuda_runtime.h>
#include <cuda_bf16.h>

// Problem constants (fixed by the reference)
#define BB  4
#define LL  512
#define HH  768
#define SS  100
#define RR  100
#define EE  25
#define NEC 10              // entity classes
#define NRC 6               // relation classes
#define NEGV (-1e20f)

#define H4       (HH/4)         // 192 float4 lanes per hidden row
#define NENT     (BB*SS)        // 400
#define NREL     (BB*RR)        // 400
#define NROW     (NEC + 2*NRC)  // 22 projection rows per entity block

static __device__ __forceinline__ float4 fmax4(float4 a, float4 b) {
    a.x = fmaxf(a.x, b.x); a.y = fmaxf(a.y, b.y);
    a.z = fmaxf(a.z, b.z); a.w = fmaxf(a.w, b.w);
    return a;
}

// masked max pool over a contiguous span, this thread's float4 lane
static __device__ __forceinline__
float4 pool_span(const float4* __restrict__ hb, int start, int len)
{
    float4 mx = make_float4(NEGV, NEGV, NEGV, NEGV);
    int l = start;
    const int e = start + len;
    for (; l + 4 <= e; l += 4) {
        float4 v0 = hb[(size_t)(l+0) * H4];
        float4 v1 = hb[(size_t)(l+1) * H4];
        float4 v2 = hb[(size_t)(l+2) * H4];
        float4 v3 = hb[(size_t)(l+3) * H4];
        mx = fmax4(mx, fmax4(fmax4(v0, v1), fmax4(v2, v3)));
    }
    for (; l < e; ++l)
        mx = fmax4(mx, hb[(size_t)l * H4]);
    return mx;
}

// contiguous 0/1 span scan: (start,len) via ballot + shared atomics
static __device__ __forceinline__
void scan_span(const int* __restrict__ mrow, int t, int warp, int lane,
               int* s_start, int* s_len)
{
    const int m0 = mrow[t];
    const int m1 = mrow[t + 256];
    if (t == 0) { *s_start = LL; *s_len = 0; }
    __syncthreads();
    unsigned b0 = __ballot_sync(0xffffffffu, m0 != 0);
    unsigned b1 = __ballot_sync(0xffffffffu, m1 != 0);
    if (lane == 0) {
        int cnt = __popc(b0) + __popc(b1);
        if (cnt) {
            int st = b0 ? (warp << 5) + __ffs(b0) - 1
                        : 256 + (warp << 5) + __ffs(b1) - 1;
            atomicMin(s_start, st);
            atomicAdd(s_len, cnt);
        }
    }
    __syncthreads();
}

// graph-safe static scratch
__device__ float g_p1[NENT*NRC];   // head projections per entity
__device__ float g_p2[NENT*NRC];   // tail projections per entity
__device__ int   g_flag[NENT];     // per-entity "p1/p2 ready" flags (0-init)
__device__ int   g_cdone = 0;      // ctx-blocks-consumed counter

// -----------------------------------------------------------------------------
// ONE kernel, 800 blocks.
//   blocks [0,400):   entity — pool + 22 in-register projections
//                     -> entity logits (out), g_p1, g_p2, then set g_flag[idx]
//   blocks [400,800): ctx — pool + 6 in-register dots, then wait on the TWO
//                     entity flags it needs (they finish much earlier),
//                     gather p1[head]+p2[tail], write relation logits.
// Last ctx block to finish resets flags/counter for the next graph replay.
// -----------------------------------------------------------------------------
__global__ void __launch_bounds__(256)
spert_fused_kernel(const float* __restrict__ hid,
                   const int*   __restrict__ emask,
                   const int*   __restrict__ rel,
                   const int*   __restrict__ cmask,
                   const float* __restrict__ size_emb,
                   const float* __restrict__ w_span,
                   const float* __restrict__ b_span,
                   const float* __restrict__ w_rel,
                   const float* __restrict__ b_rel,
                   float*       __restrict__ out)
{
    __shared__ float sred[8][NROW];
    __shared__ int s_start, s_len, s_last;

    const int bid  = blockIdx.x;
    const int t    = threadIdx.x;
    const int warp = t >> 5, lane = t & 31;
    const bool is_ent = (bid < NENT);
    const int idx  = is_ent ? bid : bid - NENT;   // b*N + n
    const int b    = idx / SS;

    // relation pair indices (ctx blocks only) — issue load early
    int hi = 0, ti = 0;
    if (!is_ent) { hi = rel[idx*2 + 0]; ti = rel[idx*2 + 1]; }

    scan_span((is_ent ? emask : cmask) + (size_t)idx * LL, t, warp, lane,
              &s_start, &s_len);
    const int start = s_start;
    const int len   = s_len;

    if (is_ent) {
        // ================= ENTITY BLOCK =================
        float acc[NROW];
        #pragma unroll
        for (int r = 0; r < NROW; ++r) acc[r] = 0.f;

        if (t < H4) {
            const float4* hb = reinterpret_cast<const float4*>(hid + (size_t)b * LL * HH) + t;
            const float4 mx = pool_span(hb, start, len);
            float rv[4] = {mx.x, mx.y, mx.z, mx.w};

            // span: w_span rows 4t..4t+3 (40 contiguous floats)
            {
                float w40[40];
                const float4* wp = reinterpret_cast<const float4*>(w_span + 40*t);
                #pragma unroll
                for (int q = 0; q < 10; ++q)
                    *reinterpret_cast<float4*>(w40 + 4*q) = wp[q];
                #pragma unroll
                for (int r = 0; r < 4; ++r)
                    #pragma unroll
                    for (int j = 0; j < NEC; ++j)
                        acc[j] += rv[r] * w40[r*NEC + j];
            }
            // head: w_rel rows 768+4t; tail: rows 1536+4t (24 floats each)
            #pragma unroll
            for (int g = 0; g < 2; ++g) {
                float w24[24];
                const int row0 = (g + 1)*HH + 4*t;
                const float4* wp = reinterpret_cast<const float4*>(w_rel + row0*NRC);
                #pragma unroll
                for (int q = 0; q < 6; ++q)
                    *reinterpret_cast<float4*>(w24 + 4*q) = wp[q];
                const int base = NEC + g*NRC;
                #pragma unroll
                for (int r = 0; r < 4; ++r)
                    #pragma unroll
                    for (int j = 0; j < NRC; ++j)
                        acc[base + j] += rv[r] * w24[r*NRC + j];
            }
        } else if (t < 199) {
            // size-embedding dims d = 4t-768 .. +3 (valid d < 25)
            const int d0 = 4*t - HH;
            const float* se = size_emb + len * EE;
            #pragma unroll
            for (int q = 0; q < 4; ++q) {
                const int d = d0 + q;
                if (d < EE) {
                    const float sv = se[d];
                    #pragma unroll
                    for (int j = 0; j < NEC; ++j)
                        acc[j] += sv * w_span[(HH + d)*NEC + j];
                    #pragma unroll
                    for (int j = 0; j < NRC; ++j) {
                        acc[NEC + j]       += sv * w_rel[(3*HH + d)*NRC + j];
                        acc[NEC + NRC + j] += sv * w_rel[(3*HH + EE + d)*NRC + j];
                    }
                }
            }
        }

        #pragma unroll
        for (int r = 0; r < NROW; ++r) {
            float v = acc[r];
            #pragma unroll
            for (int o = 16; o; o >>= 1) v += __shfl_down_sync(0xffffffffu, v, o);
            if (lane == 0) sred[warp][r] = v;
        }
        __syncthreads();
        if (t < NROW) {
            float s = 0.f;
            #pragma unroll
            for (int w = 0; w < 8; ++w) s += sred[w][t];
            if      (t < NEC)       out[idx*NEC + t]                = s + b_span[t];
            else if (t < NEC + NRC) g_p1[idx*NRC + (t - NEC)]       = s;
            else                    g_p2[idx*NRC + (t - NEC - NRC)] = s;
        }
        // publish: p1/p2 stores -> fence -> barrier -> flag
        __threadfence();
        __syncthreads();
        if (t == 0) atomicExch(&g_flag[idx], 1);
        return;
    }

    // ================= CTX BLOCK =================
    float acc[NRC];
    #pragma unroll
    for (int j = 0; j < NRC; ++j) acc[j] = 0.f;

    if (t < H4) {
        const float4* hb = reinterpret_cast<const float4*>(hid + (size_t)b * LL * HH) + t;
        const float4 mx = pool_span(hb, start, len);
        float rv[4] = {mx.x, mx.y, mx.z, mx.w};

        float w24[24];
        const float4* wp = reinterpret_cast<const float4*>(w_rel + 4*t*NRC);
        #pragma unroll
        for (int q = 0; q < 6; ++q)
            *reinterpret_cast<float4*>(w24 + 4*q) = wp[q];
        #pragma unroll
        for (int r = 0; r < 4; ++r)
            #pragma unroll
            for (int j = 0; j < NRC; ++j)
                acc[j] += rv[r] * w24[r*NRC + j];
    }

    #pragma unroll
    for (int j = 0; j < NRC; ++j) {
        float v = acc[j];
        #pragma unroll
        for (int o = 16; o; o >>= 1) v += __shfl_down_sync(0xffffffffu, v, o);
        if (lane == 0) sred[warp][j] = v;
    }
    __syncthreads();

    // wait for the TWO entity blocks this relation needs (normally already done)
    if (t == 0) {
        volatile int* f1 = &g_flag[b*SS + hi];
        volatile int* f2 = &g_flag[b*SS + ti];
        while (*f1 == 0) __nanosleep(20);
        while (*f2 == 0) __nanosleep(20);
        __threadfence();   // acquire: order p1/p2 reads after observed flags
    }
    __syncthreads();

    if (t < NRC) {
        float s = 0.f;
        #pragma unroll
        for (int w = 0; w < 8; ++w) s += sred[w][t];
        out[NENT*NEC + idx*NRC + t] = s
                                    + g_p1[(b*SS + hi)*NRC + t]
                                    + g_p2[(b*SS + ti)*NRC + t]
                                    + b_rel[t];
    }

    // replay-safe reset: last ctx block (after ALL ctx blocks consumed flags)
    __syncthreads();
    if (t == 0)
        s_last = (atomicAdd(&g_cdone, 1) == NREL - 1) ? 1 : 0;
    __syncthreads();
    if (s_last) {
        for (int i = t; i < NENT; i += 256) g_flag[i] = 0;
        if (t == 0) g_cdone = 0;
    }
}

// -----------------------------------------------------------------------------
// kernel_launch: inputs per metadata order:
//   0 hidden_states (f32)  1 entity_masks (i32)  2 relations (i32)
//   3 relation_context_masks (i32)  4 size_emb (f32)
//   5 w_span (f32)  6 b_span (f32)  7 w_rel (f32)  8 b_rel (f32)
// out: 6400 f32 = entity_logits (4000) ++ relation_logits (2400)
// -----------------------------------------------------------------------------
extern "C" void kernel_launch(void* const* d_in, const int* in_sizes, int n_in,
                              void* d_out, int out_size)
{
    const float* hid      = (const float*)d_in[0];
    const int*   emask    = (const int*)  d_in[1];
    const int*   rel      = (const int*)  d_in[2];
    const int*   cmask    = (const int*)  d_in[3];
    const float* size_emb = (const float*)d_in[4];
    const float* w_span   = (const float*)d_in[5];
    const float* b_span   = (const float*)d_in[6];
    const float* w_rel    = (const float*)d_in[7];
    const float* b_rel    = (const float*)d_in[8];
    float* out = (float*)d_out;

    spert_fused_kernel<<<NENT + NREL, 256>>>(hid, emask, rel, cmask, size_emb,
                                             w_span, b_span, w_rel, b_rel, out);
}